// round 3
// baseline (speedup 1.0000x reference)
#include <cuda_runtime.h>
#include <cuda_bf16.h>
#include <math.h>
#include <stdint.h>

// Problem dims
#define T_  512
#define B_  64
#define E_  300
#define H_  512
#define L_  5
#define G3H 1536
#define M_  (T_*B_)          // 32768

// ---------------------------------------------------------------------------
// Scratch (device globals — no runtime allocation allowed)
// ---------------------------------------------------------------------------
__device__ float g_xp0[(size_t)M_ * G3H];
__device__ float g_xp1[(size_t)M_ * G3H];
__device__ float g_h1 [(size_t)M_ * H_];
__device__ float g_h2 [(size_t)M_ * H_];
__device__ unsigned g_ctr[512];

// ---------------------------------------------------------------------------
// helpers
// ---------------------------------------------------------------------------
__device__ __forceinline__ unsigned long long pk2(float lo, float hi) {
    unsigned long long r;
    asm("mov.b64 %0, {%1, %2};" : "=l"(r) : "f"(lo), "f"(hi));
    return r;
}
__device__ __forceinline__ void fma2(unsigned long long& acc,
                                     unsigned long long a, unsigned long long b) {
    asm("fma.rn.f32x2 %0, %1, %2, %0;" : "+l"(acc) : "l"(a), "l"(b));
}
__device__ __forceinline__ float2 unpk(unsigned long long v) {
    float x, y;
    asm("mov.b64 {%0, %1}, %2;" : "=f"(x), "=f"(y) : "l"(v));
    return make_float2(x, y);
}
__device__ __forceinline__ unsigned ld_acquire(const unsigned* p) {
    unsigned v;
    asm volatile("ld.acquire.gpu.u32 %0, [%1];" : "=r"(v) : "l"(p) : "memory");
    return v;
}
__device__ __forceinline__ float sigmoidf_(float x) {
    return 1.0f / (1.0f + __expf(-x));
}
__device__ __forceinline__ float tanhf_(float x) {
    // tanh(x) = 1 - 2/(exp(2x)+1); __expf saturates to inf/0 -> correct +-1 limits
    return 1.0f - 2.0f / (__expf(2.0f * x) + 1.0f);
}

union F4U { float4 f; unsigned long long u[2]; };
union F2U { float2 f; unsigned long long u; };

__global__ void init_ctr_kernel() {
    g_ctr[threadIdx.x] = 0u;
}

// ---------------------------------------------------------------------------
// Projection GEMM: C[M,1536] = A[M,K] @ W[1536,K]^T + bias
// 128(M) x 128(N) tile, BK=16, 256 threads, per-thread 8x8 via f32x2 (m-paired)
// ---------------------------------------------------------------------------
template <bool GATHER, int K>
__global__ __launch_bounds__(256) void proj_kernel(
    const float* __restrict__ Aparam, const int* __restrict__ gidx,
    const float* __restrict__ W, const float* __restrict__ bias)
{
    __shared__ float As[16][128];
    __shared__ float Bs[16][128];

    const float* Abase = GATHER ? Aparam : g_h1;
    float* C = GATHER ? g_xp0 : g_xp1;

    const int tid = threadIdx.x;
    const int tx = tid & 15;          // n group (8 cols: tx*8)
    const int ty = tid >> 4;          // m group (8 rows: ty*8)
    const int m0 = blockIdx.y * 128;
    const int n0 = blockIdx.x * 128;

    unsigned long long acc[4][8];     // 4 m-pairs x 8 n
#pragma unroll
    for (int i = 0; i < 4; ++i)
#pragma unroll
        for (int j = 0; j < 8; ++j) acc[i][j] = 0ull;

    const int KT = (K + 15) >> 4;
    for (int kt = 0; kt < KT; ++kt) {
        const int k0 = kt << 4;
        // ---- A tile -> As[k][m] : 2048 floats, 2 float4 per thread ----
#pragma unroll
        for (int p = 0; p < 2; ++p) {
            int v  = tid + p * 256;
            int m  = v & 127;
            int kq = v >> 7;                      // 0..3
            int k  = k0 + kq * 4;
            float4 av = make_float4(0.f, 0.f, 0.f, 0.f);
            if (k < K) {
                const float* arow;
                if (GATHER) arow = Abase + (size_t)__ldg(gidx + m0 + m) * K;
                else        arow = Abase + (size_t)(m0 + m) * K;
                av = *(const float4*)(arow + k);
            }
            As[kq*4+0][m] = av.x; As[kq*4+1][m] = av.y;
            As[kq*4+2][m] = av.z; As[kq*4+3][m] = av.w;
        }
        // ---- B tile -> Bs[k][n] : 2048 floats ----
#pragma unroll
        for (int p = 0; p < 2; ++p) {
            int v  = tid + p * 256;
            int n  = v & 127;
            int kq = v >> 7;
            int k  = k0 + kq * 4;
            float4 bv = make_float4(0.f, 0.f, 0.f, 0.f);
            if (k < K) bv = *(const float4*)(W + (size_t)(n0 + n) * K + k);
            Bs[kq*4+0][n] = bv.x; Bs[kq*4+1][n] = bv.y;
            Bs[kq*4+2][n] = bv.z; Bs[kq*4+3][n] = bv.w;
        }
        __syncthreads();
        // ---- compute ----
#pragma unroll
        for (int k = 0; k < 16; ++k) {
            const float* ar = &As[k][ty * 8];
            unsigned long long a0 = *(const unsigned long long*)(ar + 0);
            unsigned long long a1 = *(const unsigned long long*)(ar + 2);
            unsigned long long a2 = *(const unsigned long long*)(ar + 4);
            unsigned long long a3 = *(const unsigned long long*)(ar + 6);
            float4 bv0 = *(const float4*)&Bs[k][tx * 8];
            float4 bv1 = *(const float4*)&Bs[k][tx * 8 + 4];
            unsigned long long b[8];
            b[0] = pk2(bv0.x, bv0.x); b[1] = pk2(bv0.y, bv0.y);
            b[2] = pk2(bv0.z, bv0.z); b[3] = pk2(bv0.w, bv0.w);
            b[4] = pk2(bv1.x, bv1.x); b[5] = pk2(bv1.y, bv1.y);
            b[6] = pk2(bv1.z, bv1.z); b[7] = pk2(bv1.w, bv1.w);
#pragma unroll
            for (int n = 0; n < 8; ++n) {
                fma2(acc[0][n], a0, b[n]);
                fma2(acc[1][n], a1, b[n]);
                fma2(acc[2][n], a2, b[n]);
                fma2(acc[3][n], a3, b[n]);
            }
        }
        __syncthreads();
    }

    // ---- epilogue ----
    float4 bb0 = *(const float4*)(bias + n0 + tx * 8);
    float4 bb1 = *(const float4*)(bias + n0 + tx * 8 + 4);
    float bb[8] = {bb0.x, bb0.y, bb0.z, bb0.w, bb1.x, bb1.y, bb1.z, bb1.w};
#pragma unroll
    for (int j = 0; j < 4; ++j) {
        float lo[8], hi[8];
#pragma unroll
        for (int n = 0; n < 8; ++n) {
            float2 u = unpk(acc[j][n]);
            lo[n] = u.x + bb[n];
            hi[n] = u.y + bb[n];
        }
        int m = m0 + ty * 8 + 2 * j;
        float* c0 = C + (size_t)m       * G3H + n0 + tx * 8;
        float* c1 = C + (size_t)(m + 1) * G3H + n0 + tx * 8;
        *(float4*)(c0)     = make_float4(lo[0], lo[1], lo[2], lo[3]);
        *(float4*)(c0 + 4) = make_float4(lo[4], lo[5], lo[6], lo[7]);
        *(float4*)(c1)     = make_float4(hi[0], hi[1], hi[2], hi[3]);
        *(float4*)(c1 + 4) = make_float4(hi[4], hi[5], hi[6], hi[7]);
    }
}

// ---------------------------------------------------------------------------
// Persistent GRU recurrence.
// 128 CTAs = 8 groups x 16 CTAs; group g owns batch rows [8g, 8g+8).
// CTA (gidx) owns hidden slice [gidx*32, gidx*32+32).
// Weight slice SMEM-resident, TRANSPOSED + k-pair packed:
//   ws_p[kk2][row] (float2), kk2 = k/2 in 0..255, row = gate*32 + li in 0..95.
//   Warp lanes read consecutive float2 -> conflict-free 256B wavefronts.
// ---------------------------------------------------------------------------
#define WSP_F2   (256 * 96)                     // float2 elements (196608 B)
#define HS_F     4096                           // hs[8][512]
#define RED_F    3072                           // red[4][3][8][32]
#define SMEM_REC_BYTES (WSP_F2 * 8 + HS_F * 4 + RED_F * 4 + 96 * 4)  // 225664 B

__global__ __launch_bounds__(256, 1) void rec_kernel(
    const float* __restrict__ Whh, const float* __restrict__ bhh, int layer)
{
    extern __shared__ float sm[];
    float2* ws_p = (float2*)sm;                       // [256][96]
    float*  hs   = sm + WSP_F2 * 2;                   // [8][512]
    float*  red  = hs + HS_F;                         // [4][3][8][32]
    float*  sb   = red + RED_F;                       // [96]

    const float* xp = layer ? g_xp1 : g_xp0;
    float*       ys = layer ? g_h2  : g_h1;

    const int tid   = threadIdx.x;
    const int wid   = tid >> 5;            // 0..7 = k-slice (64 k each)
    const int li    = tid & 31;
    const int bid   = blockIdx.x;
    const int group = bid >> 4;
    const int gidx  = bid & 15;
    const int rb    = group * 8;
    const int ibase = gidx * 32;
    unsigned* ctr   = g_ctr + layer * 256 + group * 32;

    // ---- preload weight slice (transposed) + bias slice ----
    for (int idx = tid; idx < 96 * 256; idx += 256) {
        int r   = idx >> 8;                        // 0..95
        int kk2 = idx & 255;                       // 0..255
        int gr  = (r >> 5) * 512 + ibase + (r & 31);
        float2 v = *(const float2*)(Whh + (size_t)gr * 512 + kk2 * 2);
        ws_p[kk2 * 96 + r] = v;
    }
    if (tid < 96) {
        int gr = (tid >> 5) * 512 + ibase + (tid & 31);
        sb[tid] = __ldg(bhh + gr);
    }
    __syncthreads();

    const int kbase = wid * 64;
    const int eb = tid >> 5;               // elementwise batch row
    const int ei = tid & 31;               // elementwise hidden idx in slice

    for (int t = 0; t < T_; ++t) {
        // ---- prefetch xp for this step ----
        const float* xrow = xp + ((size_t)t * B_ + rb + eb) * G3H + ibase + ei;
        float xr = __ldg(xrow);
        float xz = __ldg(xrow + 512);
        float xn = __ldg(xrow + 1024);

        // ---- stage h_{t-1} ----
        if (t == 0) {
            for (int idx = tid; idx < HS_F; idx += 256) hs[idx] = 0.f;
        } else {
            const float* hp = ys + (size_t)(t - 1) * B_ * H_ + (size_t)rb * H_;
#pragma unroll
            for (int q = 0; q < 4; ++q) {
                int idx = tid + q * 256;
                int b = idx >> 7, kv = idx & 127;
                float4 v = __ldcg((const float4*)(hp + (size_t)b * H_ + kv * 4));
                *(float4*)(hs + b * 512 + kv * 4) = v;
            }
        }
        __syncthreads();

        // ---- matvec partials over this warp's 64 k ----
        unsigned long long acc[3][8];
#pragma unroll
        for (int g = 0; g < 3; ++g)
#pragma unroll
            for (int b = 0; b < 8; ++b) acc[g][b] = 0ull;

#pragma unroll 4
        for (int it = 0; it < 16; ++it) {
            const int k4  = kbase + it * 4;
            const int kk2 = k4 >> 1;
            unsigned long long h01[8], h23[8];
#pragma unroll
            for (int b = 0; b < 8; ++b) {
                F4U hv;
                hv.f = *(const float4*)(hs + b * 512 + k4);
                h01[b] = hv.u[0];
                h23[b] = hv.u[1];
            }
#pragma unroll
            for (int g = 0; g < 3; ++g) {
                F2U wa, wb;
                wa.f = ws_p[kk2 * 96 + g * 32 + li];
                wb.f = ws_p[(kk2 + 1) * 96 + g * 32 + li];
#pragma unroll
                for (int b = 0; b < 8; ++b) {
                    fma2(acc[g][b], wa.u, h01[b]);
                    fma2(acc[g][b], wb.u, h23[b]);
                }
            }
        }

        float v[3][8];
#pragma unroll
        for (int g = 0; g < 3; ++g)
#pragma unroll
            for (int b = 0; b < 8; ++b) {
                float2 u = unpk(acc[g][b]);
                v[g][b] = u.x + u.y;
            }

        // ---- two-pass cross-warp reduction into red ----
        if (wid < 4) {
#pragma unroll
            for (int g = 0; g < 3; ++g)
#pragma unroll
                for (int b = 0; b < 8; ++b)
                    red[((wid * 3 + g) * 8 + b) * 32 + li] = v[g][b];
        }
        __syncthreads();
        if (wid >= 4) {
            int kq = wid - 4;
#pragma unroll
            for (int g = 0; g < 3; ++g)
#pragma unroll
                for (int b = 0; b < 8; ++b)
                    red[((kq * 3 + g) * 8 + b) * 32 + li] += v[g][b];
        }
        __syncthreads();

        // ---- elementwise ----
        float ghr = 0.f, ghz = 0.f, ghn = 0.f;
#pragma unroll
        for (int kq = 0; kq < 4; ++kq) {
            ghr += red[((kq * 3 + 0) * 8 + eb) * 32 + ei];
            ghz += red[((kq * 3 + 1) * 8 + eb) * 32 + ei];
            ghn += red[((kq * 3 + 2) * 8 + eb) * 32 + ei];
        }
        ghr += sb[ei];
        ghz += sb[32 + ei];
        ghn += sb[64 + ei];

        float r = sigmoidf_(xr + ghr);
        float z = sigmoidf_(xz + ghz);
        float n = tanhf_(xn + r * ghn);
        float hprev = hs[eb * 512 + ibase + ei];
        float hnew = n + z * (hprev - n);

        __stcg(ys + ((size_t)t * B_ + rb + eb) * H_ + ibase + ei, hnew);

        // ---- group barrier ----
        __threadfence();
        __syncthreads();
        if (tid == 0) {
            atomicAdd(ctr, 1u);
            unsigned target = 16u * (unsigned)(t + 1);
            while (ld_acquire(ctr) < target) { }
        }
        __syncthreads();
    }
}

// ---------------------------------------------------------------------------
// Pool over batch + FC
// ---------------------------------------------------------------------------
__global__ __launch_bounds__(256) void pool_fc_kernel(
    const float* __restrict__ fcW, const float* __restrict__ fcb,
    float* __restrict__ out)
{
    __shared__ float rbuf[5][256];
    const int t = blockIdx.x;
    const int tid = threadIdx.x;

    float s0 = 0.f, s1 = 0.f;
    const float* base = g_h2 + (size_t)t * B_ * H_ + tid * 2;
#pragma unroll 8
    for (int b = 0; b < B_; ++b) {
        float2 vv = *(const float2*)(base + (size_t)b * H_);
        s0 += vv.x; s1 += vv.y;
    }
    s0 *= (1.0f / 64.0f);
    s1 *= (1.0f / 64.0f);

#pragma unroll
    for (int l = 0; l < L_; ++l)
        rbuf[l][tid] = s0 * __ldg(fcW + l * H_ + tid * 2)
                     + s1 * __ldg(fcW + l * H_ + tid * 2 + 1);
    __syncthreads();

    for (int s = 128; s > 0; s >>= 1) {
        if (tid < s) {
#pragma unroll
            for (int l = 0; l < L_; ++l) rbuf[l][tid] += rbuf[l][tid + s];
        }
        __syncthreads();
    }
    if (tid < L_) out[t * L_ + tid] = rbuf[tid][0] + __ldg(fcb + tid);
}

// ---------------------------------------------------------------------------
// launcher
// ---------------------------------------------------------------------------
extern "C" void kernel_launch(void* const* d_in, const int* in_sizes, int n_in,
                              void* d_out, int out_size) {
    (void)in_sizes; (void)n_in; (void)out_size;
    const int*   texts = (const int*)  d_in[0];
    const float* emb   = (const float*)d_in[1];
    const float* Wih0  = (const float*)d_in[2];
    const float* Whh0  = (const float*)d_in[3];
    const float* bih0  = (const float*)d_in[4];
    const float* bhh0  = (const float*)d_in[5];
    const float* Wih1  = (const float*)d_in[6];
    const float* Whh1  = (const float*)d_in[7];
    const float* bih1  = (const float*)d_in[8];
    const float* bhh1  = (const float*)d_in[9];
    const float* fcW   = (const float*)d_in[10];
    const float* fcb   = (const float*)d_in[11];
    float* out = (float*)d_out;

    cudaFuncSetAttribute(rec_kernel,
                         cudaFuncAttributeMaxDynamicSharedMemorySize,
                         SMEM_REC_BYTES);

    init_ctr_kernel<<<1, 512>>>();
    proj_kernel<true, 300><<<dim3(12, 256), 256>>>(emb, texts, Wih0, bih0);
    rec_kernel<<<128, 256, SMEM_REC_BYTES>>>(Whh0, bhh0, 0);
    proj_kernel<false, 512><<<dim3(12, 256), 256>>>(nullptr, nullptr, Wih1, bih1);
    rec_kernel<<<128, 256, SMEM_REC_BYTES>>>(Whh1, bhh1, 1);
    pool_fc_kernel<<<512, 256>>>(fcW, fcb, out);
}